// round 6
// baseline (speedup 1.0000x reference)
#include <cuda_runtime.h>
#include <math.h>
#include <stdint.h>

// Problem constants: B=8, N=4096, C=512, NH=8, HD=64, R=8, H=W=64, M=64, EPS=1e-3

#define NB   8
#define NSEQ 4096
#define CD   512
#define NHH  8

// ---------------- scratch (device globals; no allocation allowed) ----------------
__device__ float g_q[(size_t)NB * NSEQ * CD];      // [B, N, nh*64+hd]
__device__ float g_attn[(size_t)NB * NSEQ * CD];   // [B, N, nh*64+hd]
__device__ float g_fpart[(size_t)8 * 512 * 512];   // conv partials per ry split
__device__ float g_ln[512 * 512];                  // layernormed fmap [B*64, C]
__device__ float g_kv[512 * 1024];                 // [B*64, 2C]
__device__ float g_wqp[512 * 512];                 // permuted Wq

// ---------------- helpers ----------------
__device__ __forceinline__ uint32_t f2tf32(float v) {
    uint32_t u;
    asm("cvt.rna.tf32.f32 %0, %1;" : "=r"(u) : "f"(v));
    return u;
}

__device__ __forceinline__ void mma_tf32(float* d, const uint32_t* a, const uint32_t* b) {
    asm volatile(
        "mma.sync.aligned.m16n8k8.row.col.f32.tf32.tf32.f32 "
        "{%0,%1,%2,%3}, {%4,%5,%6,%7}, {%8,%9}, {%0,%1,%2,%3};"
        : "+f"(d[0]), "+f"(d[1]), "+f"(d[2]), "+f"(d[3])
        : "r"(a[0]), "r"(a[1]), "r"(a[2]), "r"(a[3]), "r"(b[0]), "r"(b[1]));
}

// ---------------- Wq column permutation ----------------
// dst col d = nh*64+hd  <-  src col hd*8+nh
__global__ void permute_wq_kernel(const float* __restrict__ Wq) {
    int i = blockIdx.x * 256 + threadIdx.x;
    int k = i >> 9;
    int d = i & 511;
    int nh = d >> 6;
    int hd = d & 63;
    g_wqp[i] = Wq[(k << 9) + (hd << 3) + nh];
}

// =====================================================================
// tf32 tensor-core GEMM: 128x128 CTA tile, BK=32, 8 warps of 64x32.
// smem fragment-major layout:
//   As[k8][mi][lane][reg]  (4*8*32*4  = 4096 u32)
//   Bs[k8][ni][lane][reg]  (4*16*32*2 = 4096 u32)
// a-reg map (m16k8): a0=A[g][c] a1=A[g+8][c] a2=A[g][c+4] a3=A[g+8][c+4], g=lane>>2, c=lane&3
// b-reg map (k8n8):  b0=B[c][g]  b1=B[c+4][g]
// =====================================================================
__global__ __launch_bounds__(256, 2)
void tf32_gemm_kernel(const float* __restrict__ A, const float* __restrict__ B,
                      float* __restrict__ C, const float* __restrict__ bias,
                      int K, int Ncols) {
    __shared__ uint32_t As[4096];
    __shared__ uint32_t Bs[4096];
    const int tid  = threadIdx.x;
    const int lane = tid & 31, warp = tid >> 5;
    const int wm = (warp >> 2) << 6;   // 0 / 64
    const int wn = (warp & 3) << 5;    // 0..96
    const int row0 = blockIdx.x << 7;
    const int col0 = blockIdx.y << 7;

    float acc[4][4][4];
#pragma unroll
    for (int f = 0; f < 4; f++)
#pragma unroll
        for (int g = 0; g < 4; g++)
#pragma unroll
            for (int e = 0; e < 4; e++) acc[f][g][e] = 0.f;

    int ar[4], akq[4], bkr[4], bnq[4];
    const float* Ap[4];
    const float* Bp[4];
#pragma unroll
    for (int l = 0; l < 4; l++) {
        int idx = tid + (l << 8);
        ar[l]  = idx >> 3;  akq[l] = idx & 7;
        Ap[l]  = A + (size_t)(row0 + ar[l]) * K + (akq[l] << 2);
        bkr[l] = idx >> 5;  bnq[l] = idx & 31;
        Bp[l]  = B + (size_t)bkr[l] * Ncols + col0 + (bnq[l] << 2);
    }

    for (int k0 = 0; k0 < K; k0 += 32) {
#pragma unroll
        for (int l = 0; l < 4; l++) {
            float4 av = *(const float4*)(Ap[l] + k0);
            const float* avf = (const float*)&av;
            int r = ar[l], kq = akq[l];
            int rowin16 = r & 15, mi = r >> 4, g = rowin16 & 7;
#pragma unroll
            for (int j = 0; j < 4; j++) {
                int klocal = (kq << 2) + j;
                int k8 = klocal >> 3, koff = klocal & 7;
                int reg = ((koff >> 2) << 1) | (rowin16 >> 3);
                int ln2 = (g << 2) | (koff & 3);
                As[(k8 << 10) + (mi << 7) + (ln2 << 2) + reg] = f2tf32(avf[j]);
            }
            float4 bv = *(const float4*)(Bp[l] + (size_t)k0 * Ncols);
            const float* bvf = (const float*)&bv;
            int kr = bkr[l], nq = bnq[l];
            int k8b = kr >> 3, koffb = kr & 7;
            int regb = koffb >> 2, cb = koffb & 3;
#pragma unroll
            for (int j = 0; j < 4; j++) {
                int nlocal = (nq << 2) + j;
                int ni = nlocal >> 3, gb = nlocal & 7;
                int lnb = (gb << 2) | cb;
                Bs[(k8b << 10) + (ni << 6) + (lnb << 1) + regb] = f2tf32(bvf[j]);
            }
        }
        __syncthreads();
#pragma unroll
        for (int k8 = 0; k8 < 4; k8++) {
            uint32_t a[4][4], b[4][2];
#pragma unroll
            for (int f = 0; f < 4; f++)
                *(uint4*)a[f] = *(const uint4*)&As[(k8 << 10) + (((wm >> 4) + f) << 7) + (lane << 2)];
#pragma unroll
            for (int g = 0; g < 4; g++)
                *(uint2*)b[g] = *(const uint2*)&Bs[(k8 << 10) + (((wn >> 3) + g) << 6) + (lane << 1)];
#pragma unroll
            for (int f = 0; f < 4; f++)
#pragma unroll
                for (int g = 0; g < 4; g++) mma_tf32(acc[f][g], a[f], b[g]);
        }
        __syncthreads();
    }

    const int gq = lane >> 2, cq = lane & 3;
#pragma unroll
    for (int f = 0; f < 4; f++) {
        int mrow = row0 + wm + (f << 4) + gq;
#pragma unroll
        for (int g = 0; g < 4; g++) {
            int col = col0 + wn + (g << 3) + (cq << 1);
            float bx = 0.f, by = 0.f;
            if (bias) { bx = bias[col]; by = bias[col + 1]; }
            *(float2*)&C[(size_t)mrow * Ncols + col] =
                make_float2(acc[f][g][0] + bx, acc[f][g][1] + by);
            *(float2*)&C[(size_t)(mrow + 8) * Ncols + col] =
                make_float2(acc[f][g][2] + bx, acc[f][g][3] + by);
        }
    }
}

// =====================================================================
// conv as tf32 patch-GEMM (stride 8 = kernel 8, pad 0), K split by ry.
// A rows = b*64 + my*8 + mx; for fixed ry the K-slice is 4096 contiguous floats.
// grid = (4, 4, 8). Writes per-ry partials to g_fpart.
// =====================================================================
__global__ __launch_bounds__(256, 2)
void conv_tf32_kernel(const float* __restrict__ x, const float* __restrict__ W) {
    __shared__ uint32_t As[4096];
    __shared__ uint32_t Bs[4096];
    const int tid  = threadIdx.x;
    const int lane = tid & 31, warp = tid >> 5;
    const int wm = (warp >> 2) << 6;
    const int wn = (warp & 3) << 5;
    const int row0 = blockIdx.x << 7;
    const int col0 = blockIdx.y << 7;
    const int ry   = blockIdx.z;

    float acc[4][4][4];
#pragma unroll
    for (int f = 0; f < 4; f++)
#pragma unroll
        for (int g = 0; g < 4; g++)
#pragma unroll
            for (int e = 0; e < 4; e++) acc[f][g][e] = 0.f;

    int ar[4], akq[4], bkr[4], bnq[4];
    const float* Ap[4];
    const float* Bp[4];
#pragma unroll
    for (int l = 0; l < 4; l++) {
        int idx = tid + (l << 8);
        ar[l]  = idx >> 3;  akq[l] = idx & 7;
        int row = row0 + ar[l];
        int b = row >> 6, m = row & 63;
        int my = m >> 3, mx = m & 7;
        Ap[l] = x + ((size_t)(b << 12) + ((my << 3) + ry) * 64 + (mx << 3)) * 512 + (akq[l] << 2);
        bkr[l] = idx >> 5;  bnq[l] = idx & 31;
        Bp[l]  = W + ((size_t)ry * 4096 + bkr[l]) * 512 + col0 + (bnq[l] << 2);
    }

    for (int k0 = 0; k0 < 4096; k0 += 32) {
#pragma unroll
        for (int l = 0; l < 4; l++) {
            float4 av = *(const float4*)(Ap[l] + k0);
            const float* avf = (const float*)&av;
            int r = ar[l], kq = akq[l];
            int rowin16 = r & 15, mi = r >> 4, g = rowin16 & 7;
#pragma unroll
            for (int j = 0; j < 4; j++) {
                int klocal = (kq << 2) + j;
                int k8 = klocal >> 3, koff = klocal & 7;
                int reg = ((koff >> 2) << 1) | (rowin16 >> 3);
                int ln2 = (g << 2) | (koff & 3);
                As[(k8 << 10) + (mi << 7) + (ln2 << 2) + reg] = f2tf32(avf[j]);
            }
            float4 bv = *(const float4*)(Bp[l] + (size_t)k0 * 512);
            const float* bvf = (const float*)&bv;
            int kr = bkr[l], nq = bnq[l];
            int k8b = kr >> 3, koffb = kr & 7;
            int regb = koffb >> 2, cb = koffb & 3;
#pragma unroll
            for (int j = 0; j < 4; j++) {
                int nlocal = (nq << 2) + j;
                int ni = nlocal >> 3, gb = nlocal & 7;
                int lnb = (gb << 2) | cb;
                Bs[(k8b << 10) + (ni << 6) + (lnb << 1) + regb] = f2tf32(bvf[j]);
            }
        }
        __syncthreads();
#pragma unroll
        for (int k8 = 0; k8 < 4; k8++) {
            uint32_t a[4][4], b[4][2];
#pragma unroll
            for (int f = 0; f < 4; f++)
                *(uint4*)a[f] = *(const uint4*)&As[(k8 << 10) + (((wm >> 4) + f) << 7) + (lane << 2)];
#pragma unroll
            for (int g = 0; g < 4; g++)
                *(uint2*)b[g] = *(const uint2*)&Bs[(k8 << 10) + (((wn >> 3) + g) << 6) + (lane << 1)];
#pragma unroll
            for (int f = 0; f < 4; f++)
#pragma unroll
                for (int g = 0; g < 4; g++) mma_tf32(acc[f][g], a[f], b[g]);
        }
        __syncthreads();
    }

    const int gq = lane >> 2, cq = lane & 3;
#pragma unroll
    for (int f = 0; f < 4; f++) {
        int mrow = row0 + wm + (f << 4) + gq;
#pragma unroll
        for (int g = 0; g < 4; g++) {
            int col = col0 + wn + (g << 3) + (cq << 1);
            *(float2*)&g_fpart[((size_t)ry * 512 + mrow) * 512 + col] =
                make_float2(acc[f][g][0], acc[f][g][1]);
            *(float2*)&g_fpart[((size_t)ry * 512 + mrow + 8) * 512 + col] =
                make_float2(acc[f][g][2], acc[f][g][3]);
        }
    }
}

// ---------------- sum conv partials + layernorm ----------------
__device__ __forceinline__ float warpSum(float v) {
#pragma unroll
    for (int o = 16; o; o >>= 1) v += __shfl_xor_sync(0xffffffffu, v, o);
    return v;
}

__global__ void ln_kernel(const float* __restrict__ gamma, const float* __restrict__ beta) {
    const int row = blockIdx.x;       // 512 rows
    const int tid = threadIdx.x;      // 128 threads, 4 cols each
    float4 v = make_float4(0.f, 0.f, 0.f, 0.f);
#pragma unroll
    for (int z = 0; z < 8; z++) {
        float4 p = *(const float4*)&g_fpart[((size_t)z * 512 + row) * 512 + (tid << 2)];
        v.x += p.x; v.y += p.y; v.z += p.z; v.w += p.w;
    }
    float s = v.x + v.y + v.z + v.w;
    float s2 = v.x * v.x + v.y * v.y + v.z * v.z + v.w * v.w;
    s = warpSum(s);
    s2 = warpSum(s2);
    __shared__ float sh[8];
    int w = tid >> 5, l = tid & 31;
    if (l == 0) { sh[w] = s; sh[4 + w] = s2; }
    __syncthreads();
    float S  = sh[0] + sh[1] + sh[2] + sh[3];
    float S2 = sh[4] + sh[5] + sh[6] + sh[7];
    float mean = S * (1.f / 512.f);
    float var = S2 * (1.f / 512.f) - mean * mean;
    float rstd = rsqrtf(var + 1e-3f);
    float4 g = *(const float4*)&gamma[tid << 2];
    float4 be = *(const float4*)&beta[tid << 2];
    float4 o;
    o.x = (v.x - mean) * rstd * g.x + be.x;
    o.y = (v.y - mean) * rstd * g.y + be.y;
    o.z = (v.z - mean) * rstd * g.z + be.z;
    o.w = (v.w - mean) * rstd * g.w + be.w;
    *(float4*)&g_ln[(size_t)row * 512 + (tid << 2)] = o;
}

// ---------------- attention: per (b, nh), M=64 K/V resident in shared ----------------
#define ATT_SMEM ((4096 + 4096 + 128 * 65) * 4)

__global__ void attention_kernel(const float* __restrict__ q,
                                 const float* __restrict__ kv,
                                 float* __restrict__ out) {
    extern __shared__ float sm[];
    float* ks = sm;
    float* vs = sm + 4096;
    float* ps = sm + 8192;

    const int b  = blockIdx.z;
    const int nh = blockIdx.y;
    const int n0 = blockIdx.x << 7;
    const int tid = threadIdx.x;

    for (int i = tid; i < 1024; i += 128) {
        int m = i >> 4, h4 = i & 15;
        const float* base = kv + (size_t)((b << 6) + m) * 1024 + (nh << 6);
        ((float4*)ks)[i] = ((const float4*)base)[h4];
        ((float4*)vs)[i] = ((const float4*)(base + 512))[h4];
    }
    __syncthreads();

    const int row = n0 + tid;
    const float* qsrc = q + ((size_t)(b << 12) + row) * 512 + (nh << 6);
    float4 qr[16];
#pragma unroll
    for (int i = 0; i < 16; i++) qr[i] = ((const float4*)qsrc)[i];

    float maxv = -1e30f;
    for (int m = 0; m < 64; m++) {
        const float4* kr = (const float4*)(ks + (m << 6));
        float acc = 0.f;
#pragma unroll
        for (int i = 0; i < 16; i++) {
            float4 kk = kr[i];
            acc += qr[i].x * kk.x + qr[i].y * kk.y + qr[i].z * kk.z + qr[i].w * kk.w;
        }
        acc *= 0.125f;
        ps[tid * 65 + m] = acc;
        maxv = fmaxf(maxv, acc);
    }
    float ssum = 0.f;
    for (int m = 0; m < 64; m++) {
        float e = __expf(ps[tid * 65 + m] - maxv);
        ps[tid * 65 + m] = e;
        ssum += e;
    }
    const float inv = 1.f / ssum;

    float4 o[16];
#pragma unroll
    for (int i = 0; i < 16; i++) o[i] = make_float4(0.f, 0.f, 0.f, 0.f);
    for (int m = 0; m < 64; m++) {
        float p = ps[tid * 65 + m] * inv;
        const float4* vr = (const float4*)(vs + (m << 6));
#pragma unroll
        for (int i = 0; i < 16; i++) {
            float4 vv = vr[i];
            o[i].x += p * vv.x; o[i].y += p * vv.y; o[i].z += p * vv.z; o[i].w += p * vv.w;
        }
    }

    float4* dst = (float4*)(out + ((size_t)(b << 12) + row) * 512 + (nh << 6));
#pragma unroll
    for (int i = 0; i < 16; i++) dst[i] = o[i];
}

// ---------------- launch ----------------
extern "C" void kernel_launch(void* const* d_in, const int* in_sizes, int n_in,
                              void* d_out, int out_size) {
    const float* x     = (const float*)d_in[0];
    const float* Wq    = (const float*)d_in[1];
    const float* Wkv   = (const float*)d_in[2];
    const float* convw = (const float*)d_in[3];
    const float* gamma = (const float*)d_in[4];
    const float* beta  = (const float*)d_in[5];
    const float* Wp    = (const float*)d_in[6];
    const float* bp    = (const float*)d_in[7];
    float* out = (float*)d_out;

    float *p_q, *p_attn, *p_ln, *p_kv, *p_wqp;
    cudaGetSymbolAddress((void**)&p_q,    g_q);
    cudaGetSymbolAddress((void**)&p_attn, g_attn);
    cudaGetSymbolAddress((void**)&p_ln,   g_ln);
    cudaGetSymbolAddress((void**)&p_kv,   g_kv);
    cudaGetSymbolAddress((void**)&p_wqp,  g_wqp);

    cudaFuncSetAttribute(attention_kernel,
                         cudaFuncAttributeMaxDynamicSharedMemorySize, ATT_SMEM);

    // 1. permute Wq columns so q comes out in [B,N, nh*64+hd]
    permute_wq_kernel<<<1024, 256>>>(Wq);
    // 2. conv as tf32 patch-GEMM, K split 8-way by ry into partial buffers
    conv_tf32_kernel<<<dim3(4, 4, 8), 256>>>(x, convw);
    // 3. sum partials + layernorm
    ln_kernel<<<512, 128>>>(gamma, beta);
    // 4. kv = ln @ Wkv   [512 x 1024]
    tf32_gemm_kernel<<<dim3(4, 8), 256>>>(p_ln, Wkv, p_kv, nullptr, 512, 1024);
    // 5. q = x @ Wq_perm [32768 x 512]
    tf32_gemm_kernel<<<dim3(256, 4), 256>>>(x, p_wqp, p_q, nullptr, 512, 512);
    // 6. attention per (b, nh)
    attention_kernel<<<dim3(32, NHH, NB), 128, ATT_SMEM>>>(p_q, p_kv, p_attn);
    // 7. final projection + bias -> d_out
    tf32_gemm_kernel<<<dim3(256, 4), 256>>>(p_attn, Wp, out, bp, 512, 512);
}

// round 7
// speedup vs baseline: 1.6598x; 1.6598x over previous
#include <cuda_runtime.h>
#include <math.h>
#include <stdint.h>

// Problem constants: B=8, N=4096, C=512, NH=8, HD=64, R=8, H=W=64, M=64, EPS=1e-3

#define NB   8
#define NSEQ 4096
#define CD   512
#define NHH  8

// ---------------- scratch (device globals; no allocation allowed) ----------------
__device__ float g_q[(size_t)NB * NSEQ * CD];      // [B, N, nh*64+hd]
__device__ float g_attn[(size_t)NB * NSEQ * CD];   // [B, N, nh*64+hd]
__device__ float g_fpart[(size_t)8 * 512 * 512];   // conv partials per ry split
__device__ float g_ln[512 * 512];                  // layernormed fmap [B*64, C]
__device__ float g_kv[512 * 1024];                 // [B*64, 2C]
__device__ float g_wqp[512 * 512];                 // permuted Wq

// ---------------- helpers ----------------
__device__ __forceinline__ uint32_t f2tf32(float v) {
    uint32_t u;
    asm("cvt.rna.tf32.f32 %0, %1;" : "=r"(u) : "f"(v));
    return u;
}

__device__ __forceinline__ void mma_tf32(float* d, const uint32_t* a, const uint32_t* b) {
    asm volatile(
        "mma.sync.aligned.m16n8k8.row.col.f32.tf32.tf32.f32 "
        "{%0,%1,%2,%3}, {%4,%5,%6,%7}, {%8,%9}, {%0,%1,%2,%3};"
        : "+f"(d[0]), "+f"(d[1]), "+f"(d[2]), "+f"(d[3])
        : "r"(a[0]), "r"(a[1]), "r"(a[2]), "r"(a[3]), "r"(b[0]), "r"(b[1]));
}

// ---------------- Wq column permutation ----------------
__global__ void permute_wq_kernel(const float* __restrict__ Wq) {
    int i = blockIdx.x * 256 + threadIdx.x;
    int k = i >> 9;
    int d = i & 511;
    int nh = d >> 6;
    int hd = d & 63;
    g_wqp[i] = Wq[(k << 9) + (hd << 3) + nh];
}

// =====================================================================
// tf32 tensor-core GEMM: 128x128 CTA tile, BK=32, 8 warps of 64x32.
// Double-buffered dynamic smem (2 x 32KB). Fragment-major layout with
// XOR swizzles:  A field ^= (k8&3)<<2   (kills 8-way STS conflicts)
//               B field ^= (ni&15)<<1   (kills 32-way STS conflicts)
// a-reg map (m16k8): a0=A[g][c] a1=A[g+8][c] a2=A[g][c+4] a3=A[g+8][c+4]
// b-reg map (k8n8):  b0=B[c][g]  b1=B[c+4][g],   lane=(g<<2)|c
// =====================================================================

// common body shared by the plain GEMM and the conv patch-GEMM via macro
#define GEMM_PREAMBLE()                                                         \
    extern __shared__ uint32_t dynsmem[];                                       \
    const int tid  = threadIdx.x;                                               \
    const int lane = tid & 31, warp = tid >> 5;                                 \
    const int wm = (warp >> 2) << 6;                                            \
    const int wn = (warp & 3) << 5;                                             \
    float acc[4][4][4];                                                         \
    _Pragma("unroll") for (int f = 0; f < 4; f++)                               \
    _Pragma("unroll") for (int g = 0; g < 4; g++)                               \
    _Pragma("unroll") for (int e = 0; e < 4; e++) acc[f][g][e] = 0.f;

__device__ __forceinline__ void sts_tile(uint32_t* As, uint32_t* Bs,
                                         const float4* sa, const float4* sb,
                                         const int* ar, const int* akq,
                                         const int* bkr, const int* bnq) {
#pragma unroll
    for (int l = 0; l < 4; l++) {
        const float* avf = (const float*)&sa[l];
        int r = ar[l], kq = akq[l];
        int rowin16 = r & 15, mi = r >> 4, g = rowin16 & 7;
#pragma unroll
        for (int j = 0; j < 4; j++) {
            int klocal = (kq << 2) + j;
            int k8 = klocal >> 3, koff = klocal & 7;
            int reg = ((koff >> 2) << 1) | (rowin16 >> 3);
            int ln2 = (g << 2) | (koff & 3);
            int fa = ((ln2 << 2) | reg) ^ ((k8 & 3) << 2);   // swizzle
            As[(k8 << 10) + (mi << 7) + fa] = f2tf32(avf[j]);
        }
        const float* bvf = (const float*)&sb[l];
        int kr = bkr[l], nq = bnq[l];
        int k8b = kr >> 3, koffb = kr & 7;
        int regb = koffb >> 2, cb = koffb & 3;
#pragma unroll
        for (int j = 0; j < 4; j++) {
            int nlocal = (nq << 2) + j;
            int ni = nlocal >> 3, gb = nlocal & 7;
            int lnb = (gb << 2) | cb;
            int fb = ((lnb << 1) | regb) ^ ((ni & 15) << 1); // swizzle
            Bs[(k8b << 10) + (ni << 6) + fb] = f2tf32(bvf[j]);
        }
    }
}

__device__ __forceinline__ void mma_phase(const uint32_t* As, const uint32_t* Bs,
                                          int wm, int wn, int lane,
                                          float acc[4][4][4]) {
#pragma unroll
    for (int k8 = 0; k8 < 4; k8++) {
        uint32_t a[4][4], b[4][2];
#pragma unroll
        for (int f = 0; f < 4; f++) {
            int off = (k8 << 10) + (((wm >> 4) + f) << 7) +
                      (((lane << 2) ^ ((k8 & 3) << 2)));
            *(uint4*)a[f] = *(const uint4*)&As[off];
        }
#pragma unroll
        for (int g = 0; g < 4; g++) {
            int ni = (wn >> 3) + g;
            int off = (k8 << 10) + (ni << 6) +
                      (((lane << 1) ^ ((ni & 15) << 1)));
            *(uint2*)b[g] = *(const uint2*)&Bs[off];
        }
#pragma unroll
        for (int f = 0; f < 4; f++)
#pragma unroll
            for (int g = 0; g < 4; g++) mma_tf32(acc[f][g], a[f], b[g]);
    }
}

__global__ __launch_bounds__(256)
void tf32_gemm_kernel(const float* __restrict__ A, const float* __restrict__ B,
                      float* __restrict__ C, const float* __restrict__ bias,
                      int K, int Ncols) {
    GEMM_PREAMBLE();
    const int row0 = blockIdx.x << 7;
    const int col0 = blockIdx.y << 7;

    int ar[4], akq[4], bkr[4], bnq[4];
    const float* Ap[4];
    const float* Bp[4];
#pragma unroll
    for (int l = 0; l < 4; l++) {
        int idx = tid + (l << 8);
        ar[l]  = idx >> 3;  akq[l] = idx & 7;
        Ap[l]  = A + (size_t)(row0 + ar[l]) * K + (akq[l] << 2);
        bkr[l] = idx >> 5;  bnq[l] = idx & 31;
        Bp[l]  = B + (size_t)bkr[l] * Ncols + col0 + (bnq[l] << 2);
    }

    float4 sa[4], sb[4];
    uint32_t* bufA[2] = {dynsmem, dynsmem + 8192};

    // prologue
#pragma unroll
    for (int l = 0; l < 4; l++) {
        sa[l] = *(const float4*)(Ap[l]);
        sb[l] = *(const float4*)(Bp[l]);
    }
    sts_tile(bufA[0], bufA[0] + 4096, sa, sb, ar, akq, bkr, bnq);
    __syncthreads();

    int cur = 0;
    const int nIter = K >> 5;
    for (int it = 1; it < nIter; it++) {
        int k0 = it << 5;
#pragma unroll
        for (int l = 0; l < 4; l++) {
            sa[l] = *(const float4*)(Ap[l] + k0);
            sb[l] = *(const float4*)(Bp[l] + (size_t)k0 * Ncols);
        }
        mma_phase(bufA[cur], bufA[cur] + 4096, wm, wn, lane, acc);
        sts_tile(bufA[cur ^ 1], bufA[cur ^ 1] + 4096, sa, sb, ar, akq, bkr, bnq);
        __syncthreads();
        cur ^= 1;
    }
    mma_phase(bufA[cur], bufA[cur] + 4096, wm, wn, lane, acc);

    const int gq = lane >> 2, cq = lane & 3;
#pragma unroll
    for (int f = 0; f < 4; f++) {
        int mrow = row0 + wm + (f << 4) + gq;
#pragma unroll
        for (int g = 0; g < 4; g++) {
            int col = col0 + wn + (g << 3) + (cq << 1);
            float bx = 0.f, by = 0.f;
            if (bias) { bx = bias[col]; by = bias[col + 1]; }
            *(float2*)&C[(size_t)mrow * Ncols + col] =
                make_float2(acc[f][g][0] + bx, acc[f][g][1] + by);
            *(float2*)&C[(size_t)(mrow + 8) * Ncols + col] =
                make_float2(acc[f][g][2] + bx, acc[f][g][3] + by);
        }
    }
}

// =====================================================================
// conv as tf32 patch-GEMM (stride 8 = kernel 8, pad 0), K split by ry.
// Same pipelined core; A rows come from x with free im2col addressing.
// grid = (4, 4, 8). Writes per-ry partials to g_fpart.
// =====================================================================
__global__ __launch_bounds__(256)
void conv_tf32_kernel(const float* __restrict__ x, const float* __restrict__ W) {
    GEMM_PREAMBLE();
    const int row0 = blockIdx.x << 7;
    const int col0 = blockIdx.y << 7;
    const int ry   = blockIdx.z;

    int ar[4], akq[4], bkr[4], bnq[4];
    const float* Ap[4];
    const float* Bp[4];
#pragma unroll
    for (int l = 0; l < 4; l++) {
        int idx = tid + (l << 8);
        ar[l]  = idx >> 3;  akq[l] = idx & 7;
        int row = row0 + ar[l];
        int b = row >> 6, m = row & 63;
        int my = m >> 3, mx = m & 7;
        Ap[l] = x + ((size_t)(b << 12) + ((my << 3) + ry) * 64 + (mx << 3)) * 512 + (akq[l] << 2);
        bkr[l] = idx >> 5;  bnq[l] = idx & 31;
        Bp[l]  = W + ((size_t)ry * 4096 + bkr[l]) * 512 + col0 + (bnq[l] << 2);
    }

    float4 sa[4], sb[4];
    uint32_t* bufA[2] = {dynsmem, dynsmem + 8192};

#pragma unroll
    for (int l = 0; l < 4; l++) {
        sa[l] = *(const float4*)(Ap[l]);
        sb[l] = *(const float4*)(Bp[l]);
    }
    sts_tile(bufA[0], bufA[0] + 4096, sa, sb, ar, akq, bkr, bnq);
    __syncthreads();

    int cur = 0;
    for (int it = 1; it < 128; it++) {
        int k0 = it << 5;
#pragma unroll
        for (int l = 0; l < 4; l++) {
            sa[l] = *(const float4*)(Ap[l] + k0);
            sb[l] = *(const float4*)(Bp[l] + (size_t)k0 * 512);
        }
        mma_phase(bufA[cur], bufA[cur] + 4096, wm, wn, lane, acc);
        sts_tile(bufA[cur ^ 1], bufA[cur ^ 1] + 4096, sa, sb, ar, akq, bkr, bnq);
        __syncthreads();
        cur ^= 1;
    }
    mma_phase(bufA[cur], bufA[cur] + 4096, wm, wn, lane, acc);

    const int gq = lane >> 2, cq = lane & 3;
#pragma unroll
    for (int f = 0; f < 4; f++) {
        int mrow = row0 + wm + (f << 4) + gq;
#pragma unroll
        for (int g = 0; g < 4; g++) {
            int col = col0 + wn + (g << 3) + (cq << 1);
            *(float2*)&g_fpart[((size_t)ry * 512 + mrow) * 512 + col] =
                make_float2(acc[f][g][0], acc[f][g][1]);
            *(float2*)&g_fpart[((size_t)ry * 512 + mrow + 8) * 512 + col] =
                make_float2(acc[f][g][2], acc[f][g][3]);
        }
    }
}

// ---------------- sum conv partials + layernorm ----------------
__device__ __forceinline__ float warpSum(float v) {
#pragma unroll
    for (int o = 16; o; o >>= 1) v += __shfl_xor_sync(0xffffffffu, v, o);
    return v;
}

__global__ void ln_kernel(const float* __restrict__ gamma, const float* __restrict__ beta) {
    const int row = blockIdx.x;
    const int tid = threadIdx.x;
    float4 v = make_float4(0.f, 0.f, 0.f, 0.f);
#pragma unroll
    for (int z = 0; z < 8; z++) {
        float4 p = *(const float4*)&g_fpart[((size_t)z * 512 + row) * 512 + (tid << 2)];
        v.x += p.x; v.y += p.y; v.z += p.z; v.w += p.w;
    }
    float s = v.x + v.y + v.z + v.w;
    float s2 = v.x * v.x + v.y * v.y + v.z * v.z + v.w * v.w;
    s = warpSum(s);
    s2 = warpSum(s2);
    __shared__ float sh[8];
    int w = tid >> 5, l = tid & 31;
    if (l == 0) { sh[w] = s; sh[4 + w] = s2; }
    __syncthreads();
    float S  = sh[0] + sh[1] + sh[2] + sh[3];
    float S2 = sh[4] + sh[5] + sh[6] + sh[7];
    float mean = S * (1.f / 512.f);
    float var = S2 * (1.f / 512.f) - mean * mean;
    float rstd = rsqrtf(var + 1e-3f);
    float4 g = *(const float4*)&gamma[tid << 2];
    float4 be = *(const float4*)&beta[tid << 2];
    float4 o;
    o.x = (v.x - mean) * rstd * g.x + be.x;
    o.y = (v.y - mean) * rstd * g.y + be.y;
    o.z = (v.z - mean) * rstd * g.z + be.z;
    o.w = (v.w - mean) * rstd * g.w + be.w;
    *(float4*)&g_ln[(size_t)row * 512 + (tid << 2)] = o;
}

// ---------------- attention: per (b, nh), M=64 K/V resident in shared ----------------
#define ATT_SMEM ((4096 + 4096 + 128 * 65) * 4)

__global__ void attention_kernel(const float* __restrict__ q,
                                 const float* __restrict__ kv,
                                 float* __restrict__ out) {
    extern __shared__ float sm[];
    float* ks = sm;
    float* vs = sm + 4096;
    float* ps = sm + 8192;

    const int b  = blockIdx.z;
    const int nh = blockIdx.y;
    const int n0 = blockIdx.x << 7;
    const int tid = threadIdx.x;

    for (int i = tid; i < 1024; i += 128) {
        int m = i >> 4, h4 = i & 15;
        const float* base = kv + (size_t)((b << 6) + m) * 1024 + (nh << 6);
        ((float4*)ks)[i] = ((const float4*)base)[h4];
        ((float4*)vs)[i] = ((const float4*)(base + 512))[h4];
    }
    __syncthreads();

    const int row = n0 + tid;
    const float* qsrc = q + ((size_t)(b << 12) + row) * 512 + (nh << 6);
    float4 qr[16];
#pragma unroll
    for (int i = 0; i < 16; i++) qr[i] = ((const float4*)qsrc)[i];

    float maxv = -1e30f;
    for (int m = 0; m < 64; m++) {
        const float4* kr = (const float4*)(ks + (m << 6));
        float acc = 0.f;
#pragma unroll
        for (int i = 0; i < 16; i++) {
            float4 kk = kr[i];
            acc += qr[i].x * kk.x + qr[i].y * kk.y + qr[i].z * kk.z + qr[i].w * kk.w;
        }
        acc *= 0.125f;
        ps[tid * 65 + m] = acc;
        maxv = fmaxf(maxv, acc);
    }
    float ssum = 0.f;
    for (int m = 0; m < 64; m++) {
        float e = __expf(ps[tid * 65 + m] - maxv);
        ps[tid * 65 + m] = e;
        ssum += e;
    }
    const float inv = 1.f / ssum;

    float4 o[16];
#pragma unroll
    for (int i = 0; i < 16; i++) o[i] = make_float4(0.f, 0.f, 0.f, 0.f);
    for (int m = 0; m < 64; m++) {
        float p = ps[tid * 65 + m] * inv;
        const float4* vr = (const float4*)(vs + (m << 6));
#pragma unroll
        for (int i = 0; i < 16; i++) {
            float4 vv = vr[i];
            o[i].x += p * vv.x; o[i].y += p * vv.y; o[i].z += p * vv.z; o[i].w += p * vv.w;
        }
    }

    float4* dst = (float4*)(out + ((size_t)(b << 12) + row) * 512 + (nh << 6));
#pragma unroll
    for (int i = 0; i < 16; i++) dst[i] = o[i];
}

// ---------------- launch ----------------
#define GEMM_SMEM (2 * 8192 * 4 * 2)   // 2 buffers x (As 4096 + Bs 4096) u32 = 64KB

extern "C" void kernel_launch(void* const* d_in, const int* in_sizes, int n_in,
                              void* d_out, int out_size) {
    const float* x     = (const float*)d_in[0];
    const float* Wq    = (const float*)d_in[1];
    const float* Wkv   = (const float*)d_in[2];
    const float* convw = (const float*)d_in[3];
    const float* gamma = (const float*)d_in[4];
    const float* beta  = (const float*)d_in[5];
    const float* Wp    = (const float*)d_in[6];
    const float* bp    = (const float*)d_in[7];
    float* out = (float*)d_out;

    float *p_q, *p_attn, *p_ln, *p_kv, *p_wqp;
    cudaGetSymbolAddress((void**)&p_q,    g_q);
    cudaGetSymbolAddress((void**)&p_attn, g_attn);
    cudaGetSymbolAddress((void**)&p_ln,   g_ln);
    cudaGetSymbolAddress((void**)&p_kv,   g_kv);
    cudaGetSymbolAddress((void**)&p_wqp,  g_wqp);

    cudaFuncSetAttribute(attention_kernel,
                         cudaFuncAttributeMaxDynamicSharedMemorySize, ATT_SMEM);
    cudaFuncSetAttribute(tf32_gemm_kernel,
                         cudaFuncAttributeMaxDynamicSharedMemorySize, GEMM_SMEM);
    cudaFuncSetAttribute(conv_tf32_kernel,
                         cudaFuncAttributeMaxDynamicSharedMemorySize, GEMM_SMEM);

    // 1. permute Wq columns so q comes out in [B,N, nh*64+hd]
    permute_wq_kernel<<<1024, 256>>>(Wq);
    // 2. conv as tf32 patch-GEMM, K split 8-way by ry into partial buffers
    conv_tf32_kernel<<<dim3(4, 4, 8), 256, GEMM_SMEM>>>(x, convw);
    // 3. sum partials + layernorm
    ln_kernel<<<512, 128>>>(gamma, beta);
    // 4. kv = ln @ Wkv   [512 x 1024]
    tf32_gemm_kernel<<<dim3(4, 8), 256, GEMM_SMEM>>>(p_ln, Wkv, p_kv, nullptr, 512, 1024);
    // 5. q = x @ Wq_perm [32768 x 512]
    tf32_gemm_kernel<<<dim3(256, 4), 256, GEMM_SMEM>>>(x, p_wqp, p_q, nullptr, 512, 512);
    // 6. attention per (b, nh)
    attention_kernel<<<dim3(32, NHH, NB), 128, ATT_SMEM>>>(p_q, p_kv, p_attn);
    // 7. final projection + bias -> d_out
    tf32_gemm_kernel<<<dim3(256, 4), 256, GEMM_SMEM>>>(p_attn, Wp, out, bp, 512, 512);
}